// round 14
// baseline (speedup 1.0000x reference)
#include <cuda_runtime.h>
#include <math.h>
#include <stdint.h>

#define BB 8
#define NN 2048
#define MM 2048
#define STRIDE 512            /* max sparse entries per row/col in gmem ELL */
#define PAIRS (STRIDE / 2)
#define NITER 100
#define CPB 8                 /* CTAs per batch */
#define SLICE 256             /* rows/cols owned per CTA */
#define RSTAGE 22             /* pair slots per thread resident in SMEM */

#define KFLOOR 1.9287498479639178e-22f   /* fp32(exp(-50)) */
#define MUV    4.8828125e-4f             /* 1/2048 */
#define EPSDIV 1e-8f

static __device__ __forceinline__ float uaf(unsigned x) { return __uint_as_float(x); }

// ---- static device scratch (no runtime allocations allowed) ----
__device__ uint4 g_rell4[(size_t)BB * PAIRS * NN];   // (j, Ktilde)    row-major ELL
__device__ uint4 g_cell4[(size_t)BB * PAIRS * MM];   // (i, Ktilde)    col-major ELL
__device__ uint4 g_eell4[(size_t)BB * PAIRS * NN];   // (j, Ktilde*d)  row-major ELL (emd)
__device__ int   g_rcnt[BB * NN];
__device__ int   g_ccnt[BB * MM];
__device__ __align__(16) float g_u[BB * NN];         // u exchange buffer (final too)
__device__ __align__(16) float g_v[BB * MM];         // v exchange buffer (final too)
__device__ unsigned g_uc[BB], g_vc[BB];              // monotone arrival counters
__device__ float g_accum;

// ---- dynamic SMEM (~196 KB) ----
struct SKm {
    float u[NN];                // replicated u (filled from gmem each phase)
    float v[MM];
    uint4 bufR[RSTAGE * 256];   // resident row entries, layout [k][tid]
    uint4 bufC[RSTAGE * 256];   // resident col entries
};

// ---- L2 flag-sync helpers ----
static __device__ __forceinline__ unsigned ld_acq(const unsigned* p) {
    unsigned v;
    asm volatile("ld.acquire.gpu.global.u32 %0, [%1];" : "=r"(v) : "l"(p) : "memory");
    return v;
}
static __device__ __forceinline__ void red_rel_add1(unsigned* p) {
    asm volatile("red.release.gpu.global.add.u32 [%0], 1;" :: "l"(p) : "memory");
}

// ---------------------------------------------------------------------------
__global__ void init_kernel() {
    int t = blockIdx.x * blockDim.x + threadIdx.x;
    if (t < BB * MM) g_ccnt[t] = 0;
    if (t < BB) { g_uc[t] = 0u; g_vc[t] = 0u; }
    if (t == 0) g_accum = 0.0f;
}

// ---------------------------------------------------------------------------
// Build sparse correction lists where d^2 < 0.25 (100*d < 50); elsewhere
// K == exp(-50) exactly (same bits as the reference clamp).
__global__ void build_kernel(const float* __restrict__ src, const float* __restrict__ tgt) {
    const int b = blockIdx.y;
    __shared__ float tx[MM], ty[MM], tz[MM];
    const float* T = tgt + (size_t)b * MM * 3;
    for (int j = threadIdx.x; j < MM; j += blockDim.x) {
        tx[j] = T[3 * j + 0];
        ty[j] = T[3 * j + 1];
        tz[j] = T[3 * j + 2];
    }
    __syncthreads();

    const int warp = threadIdx.x >> 5, lane = threadIdx.x & 31;
    const int nwarps = blockDim.x >> 5;
    const int rows_per_cta = NN / gridDim.x;
    const int row0 = blockIdx.x * rows_per_cta;
    const float* S = src + (size_t)b * NN * 3;
    uint2* rell2 = (uint2*)(g_rell4 + (size_t)b * PAIRS * NN);
    uint2* eell2 = (uint2*)(g_eell4 + (size_t)b * PAIRS * NN);
    uint2* cell2 = (uint2*)(g_cell4 + (size_t)b * PAIRS * MM);

    for (int i = row0 + warp; i < row0 + rows_per_cta; i += nwarps) {
        const float sx = S[3 * i + 0], sy = S[3 * i + 1], sz = S[3 * i + 2];
        int rbase = 0;
        for (int j0 = 0; j0 < MM; j0 += 32) {
            const int j = j0 + lane;
            float dx = sx - tx[j];
            float dy = sy - ty[j];
            float dz = sz - tz[j];
            float s = fmaf(dx, dx, fmaf(dy, dy, dz * dz));
            bool pred = (s < 0.25f);
            unsigned mask = __ballot_sync(0xffffffffu, pred);
            if (pred) {
                float d = sqrtf(s);
                float kt = expf(-100.0f * d) - KFLOOR;
                int k = rbase + __popc(mask & ((1u << lane) - 1u));
                if (k < STRIDE) {
                    size_t i2 = ((size_t)(k >> 1) * NN + i) * 2 + (k & 1);
                    rell2[i2] = make_uint2((unsigned)j, __float_as_uint(kt));
                    eell2[i2] = make_uint2((unsigned)j, __float_as_uint(kt * d));
                }
                int kc = atomicAdd(&g_ccnt[b * MM + j], 1);
                if (kc < STRIDE)
                    cell2[((size_t)(kc >> 1) * MM + j) * 2 + (kc & 1)] =
                        make_uint2((unsigned)i, __float_as_uint(kt));
            }
            rbase += __popc(mask);
        }
        int cap = (rbase < STRIDE) ? rbase : STRIDE;
        if (lane == 0) {
            g_rcnt[b * NN + i] = cap;
            if (cap & 1) {   // zero-pad ELL odd tail (cap==STRIDE is even)
                size_t i2 = ((size_t)(cap >> 1) * NN + i) * 2 + 1;
                rell2[i2] = make_uint2(0u, 0u);
                eell2[i2] = make_uint2(0u, 0u);
            }
        }
    }
}

// Clamp column counts + zero-pad odd tails of the column lists.
__global__ void colfix_kernel() {
    int t = blockIdx.x * blockDim.x + threadIdx.x;
    if (t >= BB * MM) return;
    int c = g_ccnt[t];
    if (c > STRIDE) c = STRIDE;
    g_ccnt[t] = c;
    if (c & 1) {
        int b = t / MM, j = t - b * MM;
        uint2* cell2 = (uint2*)(g_cell4 + (size_t)b * PAIRS * MM);
        cell2[((size_t)(c >> 1) * MM + j) * 2 + 1] = make_uint2(0u, 0u);
    }
}

// ---------------------------------------------------------------------------
// 64 plain CTAs (8 per batch, all co-resident in wave 1), 256 threads, one
// thread per owned row+col. ELL lists resident in SMEM (loaded once).
// Exchange via L2: STG own slice -> syncthreads -> release-red counter ->
// all threads acquire-poll -> __ldcg full 8KB -> syncthreads. No clusters.
__global__ void __launch_bounds__(256, 1)
sinkhorn_kernel() {
    extern __shared__ char raw[];
    SKm* S = (SKm*)raw;
    const int b    = blockIdx.x >> 3;
    const int rank = blockIdx.x & 7;
    const int tid  = threadIdx.x;
    const int row0 = rank * SLICE;

    for (int j = tid; j < MM; j += 256) S->v[j] = 1.0f;
    const int rnp = (g_rcnt[b * NN + row0 + tid] + 1) >> 1;   // uint4 pair slots
    const int cnp = (g_ccnt[b * MM + row0 + tid] + 1) >> 1;

    const uint4* prow = g_rell4 + (size_t)b * PAIRS * NN + (row0 + tid);
    const uint4* pcol = g_cell4 + (size_t)b * PAIRS * MM + (row0 + tid);

    // one-time preload of entry lists into SMEM (coalesced across tid)
    const int rs = (rnp < RSTAGE) ? rnp : RSTAGE;
    const int cs = (cnp < RSTAGE) ? cnp : RSTAGE;
    for (int k = 0; k < rs; k++) S->bufR[k * 256 + tid] = prow[(size_t)k * NN];
    for (int k = 0; k < cs; k++) S->bufC[k * 256 + tid] = pcol[(size_t)k * MM];

    const uint4* bR = S->bufR + tid;
    const uint4* bC = S->bufC + tid;
    const float4* gu4 = (const float4*)(g_u + (size_t)b * NN);
    const float4* gv4 = (const float4*)(g_v + (size_t)b * MM);
    float4* su4 = (float4*)S->u;
    float4* sv4 = (float4*)S->v;
    unsigned* ucp = &g_uc[b];
    unsigned* vcp = &g_vc[b];

    __syncthreads();   // lists + v=1 visible

    for (int iter = 0; iter < NITER; iter++) {
        // ---- phase A: u from v ----
        {
            float a0 = 0.0f, a1 = 0.0f;
#pragma unroll 4
            for (int pk = 0; pk < rs; pk++) {
                uint4 e = bR[pk * 256];
                a0 = fmaf(uaf(e.y), S->v[e.x], a0);
                a1 = fmaf(uaf(e.w), S->v[e.z], a1);
            }
            for (int pk = RSTAGE; pk < rnp; pk++) {   // very rare heavy-row tail
                uint4 e = prow[(size_t)pk * NN];
                a0 = fmaf(uaf(e.y), S->v[e.x], a0);
                a1 = fmaf(uaf(e.w), S->v[e.z], a1);
            }
            // KFLOOR*S_v <= 2e-14 is absorbed by the 1e-8 clamp; drop it.
            g_u[b * NN + row0 + tid] = __fdividef(MUV, fmaxf(a0 + a1, EPSDIV));
        }
        __syncthreads();                    // all 256 STGs ordered before release
        if (tid == 0) red_rel_add1(ucp);    // announce: my u slice is in L2
        {
            const unsigned tgt = 8u * (unsigned)(iter + 1);
            while (ld_acq(ucp) < tgt) {}
            float4 x0 = __ldcg(gu4 + 2 * tid);
            float4 x1 = __ldcg(gu4 + 2 * tid + 1);
            su4[2 * tid]     = x0;
            su4[2 * tid + 1] = x1;
        }
        __syncthreads();                    // full u replicated in SMEM

        // ---- phase B: v from u ----
        {
            float a0 = 0.0f, a1 = 0.0f;
#pragma unroll 4
            for (int pk = 0; pk < cs; pk++) {
                uint4 e = bC[pk * 256];
                a0 = fmaf(uaf(e.y), S->u[e.x], a0);
                a1 = fmaf(uaf(e.w), S->u[e.z], a1);
            }
            for (int pk = RSTAGE; pk < cnp; pk++) {
                uint4 e = pcol[(size_t)pk * MM];
                a0 = fmaf(uaf(e.y), S->u[e.x], a0);
                a1 = fmaf(uaf(e.w), S->u[e.z], a1);
            }
            g_v[b * MM + row0 + tid] = __fdividef(MUV, fmaxf(a0 + a1, EPSDIV));
        }
        __syncthreads();
        if (tid == 0) red_rel_add1(vcp);
        {
            const unsigned tgt = 8u * (unsigned)(iter + 1);
            while (ld_acq(vcp) < tgt) {}
            float4 x0 = __ldcg(gv4 + 2 * tid);
            float4 x1 = __ldcg(gv4 + 2 * tid + 1);
            sv4[2 * tid]     = x0;
            sv4[2 * tid + 1] = x1;
        }
        __syncthreads();
    }
    // final u/v already live in g_u/g_v (written every phase)
}

// ---------------------------------------------------------------------------
// emd_b = sum_i u_i * ( KFLOOR * sum_j d_ij v_j + sum_sparse (K~ d)_ij v_j )
__global__ void emd_kernel(const float* __restrict__ src, const float* __restrict__ tgt) {
    const int b = blockIdx.y;
    __shared__ float tx[MM], ty[MM], tz[MM], vv[MM];
    __shared__ float redw[8];
    const float* T = tgt + (size_t)b * MM * 3;
    for (int j = threadIdx.x; j < MM; j += blockDim.x) {
        tx[j] = T[3 * j + 0];
        ty[j] = T[3 * j + 1];
        tz[j] = T[3 * j + 2];
        vv[j] = g_v[b * MM + j];
    }
    __syncthreads();

    const int warp = threadIdx.x >> 5, lane = threadIdx.x & 31;
    const int nwarps = blockDim.x >> 5;
    const int rows_per_cta = NN / gridDim.x;
    const int row0 = blockIdx.x * rows_per_cta;
    const float* S = src + (size_t)b * NN * 3;
    const uint4* eell = g_eell4 + (size_t)b * PAIRS * NN;

    float wacc = 0.0f;
    for (int i = row0 + warp; i < row0 + rows_per_cta; i += nwarps) {
        const float sx = S[3 * i + 0], sy = S[3 * i + 1], sz = S[3 * i + 2];
        const float ui = g_u[b * NN + i];
        float dacc = 0.0f;
        for (int j0 = 0; j0 < MM; j0 += 32) {
            const int j = j0 + lane;
            float dx = sx - tx[j];
            float dy = sy - ty[j];
            float dz = sz - tz[j];
            float s = fmaf(dx, dx, fmaf(dy, dy, dz * dz));
            dacc = fmaf(sqrtf(s), vv[j], dacc);
        }
        float sacc = 0.0f;
        const int np = (g_rcnt[b * NN + i] + 1) >> 1;
        const uint4* p = eell + i;
        for (int pp = lane; pp < np; pp += 32) {
            uint4 e = p[(size_t)pp * NN];
            sacc = fmaf(uaf(e.y), vv[e.x], sacc);
            sacc = fmaf(uaf(e.w), vv[e.z], sacc);
        }
        float tot = fmaf(KFLOOR, dacc, sacc);
#pragma unroll
        for (int o = 16; o > 0; o >>= 1) tot += __shfl_xor_sync(0xffffffffu, tot, o);
        if (lane == 0) wacc = fmaf(ui, tot, wacc);
    }
    if (lane == 0) redw[warp] = wacc;
    __syncthreads();
    if (threadIdx.x == 0) {
        float s = 0.0f;
        for (int w = 0; w < nwarps; w++) s += redw[w];
        atomicAdd(&g_accum, s);
    }
}

__global__ void finalize_kernel(float* out) { out[0] = g_accum * (1.0f / BB); }

// ---------------------------------------------------------------------------
extern "C" void kernel_launch(void* const* d_in, const int* in_sizes, int n_in,
                              void* d_out, int out_size) {
    (void)in_sizes; (void)n_in; (void)out_size;
    const float* src = (const float*)d_in[0];
    const float* tgt = (const float*)d_in[1];
    float* out = (float*)d_out;

    cudaFuncSetAttribute(sinkhorn_kernel, cudaFuncAttributeMaxDynamicSharedMemorySize,
                         (int)sizeof(SKm));

    // 6 launches/call (same shape whose ncu capture hits sinkhorn).
    init_kernel<<<64, 256>>>();
    build_kernel<<<dim3(64, BB), 256>>>(src, tgt);
    colfix_kernel<<<64, 256>>>();
    sinkhorn_kernel<<<BB * CPB, 256, sizeof(SKm)>>>();
    emd_kernel<<<dim3(64, BB), 256>>>(src, tgt);
    finalize_kernel<<<1, 1>>>(out);
}